// round 10
// baseline (speedup 1.0000x reference)
#include <cuda_runtime.h>
#include <cuda_fp16.h>
#include <cstdint>

// ============================================================================
// BayesianLinear on sm_103 (base ISA — tcgen05 blocked by compute_103 target).
// fp16 single-pass GEMM (rel_err ~3e-4 < 1e-3, validated R6):
//   w = mu + softplus(rho)*eps -> fp16;  x -> fp16
//   out = x_f16 @ w_f16^T  (fp32 accum)  + bias
// R9 -> R10: kill the wave-quantization tail. CTA = 512 threads, 1 CTA/SM:
// 16 warps = 8 warp-tiles (64x32) x 2 K-halves; K-split reduced via smem in
// the epilogue. Grid 1024 over 148 slots -> 6.92 waves, last wave 92% full
// (was 3.46 waves, 46% full). Mainloop per warp identical to R6.
// ============================================================================

#define IN_F   4096
#define OUT_F  4096
#define BATCH  4096

// ---------------- scratch (no cudaMalloc allowed) ----------------
__device__ __align__(16) __half g_w_h[(size_t)OUT_F * IN_F];
__device__ __align__(16) __half g_x_h[(size_t)BATCH * IN_F];
__device__ __align__(16) float  g_bias[OUT_F];

// ---------------- helpers ----------------
__device__ __forceinline__ uint32_t smem_to_u32(const void* p) {
    uint32_t a;
    asm("{ .reg .u64 t; cvta.to.shared.u64 t, %1; cvt.u32.u64 %0, t; }" : "=r"(a) : "l"(p));
    return a;
}

__device__ __forceinline__ void cp16(uint32_t saddr, const void* gptr) {
    size_t ga = __cvta_generic_to_global(gptr);
    asm volatile("cp.async.cg.shared.global [%0], [%1], 16;"
                 :: "r"(saddr), "l"(ga) : "memory");
}
#define CP_COMMIT() asm volatile("cp.async.commit_group;" ::: "memory")
#define CP_WAIT1()  asm volatile("cp.async.wait_group 1;" ::: "memory")

__device__ __forceinline__ void ldsm_x4(uint32_t (&r)[4], uint32_t saddr) {
    asm volatile("ldmatrix.sync.aligned.m8n8.x4.shared.b16 {%0,%1,%2,%3}, [%4];"
                 : "=r"(r[0]), "=r"(r[1]), "=r"(r[2]), "=r"(r[3]) : "r"(saddr));
}

__device__ __forceinline__ void mma_f16(float (&d)[4], const uint32_t (&a)[4],
                                        uint32_t b0, uint32_t b1) {
    asm volatile(
        "mma.sync.aligned.m16n8k16.row.col.f32.f16.f16.f32 "
        "{%0,%1,%2,%3}, {%4,%5,%6,%7}, {%8,%9}, {%0,%1,%2,%3};"
        : "+f"(d[0]), "+f"(d[1]), "+f"(d[2]), "+f"(d[3])
        : "r"(a[0]), "r"(a[1]), "r"(a[2]), "r"(a[3]), "r"(b0), "r"(b1));
}

__device__ __forceinline__ uint32_t pack_h2(float a, float b) {
    __half ha = __float2half_rn(a);
    __half hb = __float2half_rn(b);
    return (uint32_t)__half_as_ushort(ha) | ((uint32_t)__half_as_ushort(hb) << 16);
}

// ============================================================================
// Pass 1 (fused): weight -> fp16, x -> fp16, bias -> fp32
// ============================================================================
#define WBLK (OUT_F * (IN_F / 4) / 256)   // 16384
#define XBLK (BATCH * (IN_F / 4) / 256)   // 16384
#define BBLK (OUT_F / 256)                // 16

__global__ void __launch_bounds__(256) prep_kernel(
    const float* __restrict__ x,
    const float* __restrict__ wmu, const float* __restrict__ wrho,
    const float* __restrict__ bmu, const float* __restrict__ brho,
    const float* __restrict__ weps, const float* __restrict__ beps)
{
    int b = blockIdx.x;
    if (b < WBLK) {
        size_t i4 = (size_t)b * 256 + threadIdx.x;
        const float4 m = ((const float4*)wmu)[i4];
        const float4 r = ((const float4*)wrho)[i4];
        const float4 e = ((const float4*)weps)[i4];
        float w0 = m.x + (log1pf(expf(r.x)) + 1e-8f) * e.x;
        float w1 = m.y + (log1pf(expf(r.y)) + 1e-8f) * e.y;
        float w2 = m.z + (log1pf(expf(r.z)) + 1e-8f) * e.z;
        float w3 = m.w + (log1pf(expf(r.w)) + 1e-8f) * e.w;
        ((uint2*)g_w_h)[i4] = make_uint2(pack_h2(w0, w1), pack_h2(w2, w3));
    } else if (b < WBLK + XBLK) {
        size_t i4 = (size_t)(b - WBLK) * 256 + threadIdx.x;
        const float4 v = ((const float4*)x)[i4];
        ((uint2*)g_x_h)[i4] = make_uint2(pack_h2(v.x, v.y), pack_h2(v.z, v.w));
    } else {
        int i = (b - WBLK - XBLK) * 256 + threadIdx.x;
        g_bias[i] = bmu[i] + (log1pf(expf(brho[i])) + 1e-8f) * beps[i];
    }
}

// ============================================================================
// Pass 2: GEMM. CTA 128x128, 512 threads (16 warps), 1 CTA/SM.
// 16 warps = 8 warp-tiles (64x32; wm in {0,1}, wn in {0..3}) x 2 K-halves.
// BK=64 stage, warp h covers fp16 cols [h*32, h*32+32) of the stage.
// 3-stage cp.async ring, one __syncthreads per kt. K-split reduced in smem.
// ============================================================================
#define BM 128
#define BN 128
#define BK 64
#define KPAD 72                    // fp16/row -> 144 B rows, conflict-free ldsm
#define ARR_B (128 * 144)          // 18432 B per array
#define OFF_A 0
#define OFF_B ARR_B
#define STAGE_BYTES (2 * ARR_B)    // 36864
#define NSTAGE 3
#define SMEM_SIZE (NSTAGE * STAGE_BYTES)   // 110592
#define NT (IN_F / BK)             // 64

__global__ void __launch_bounds__(512, 1) gemm_kernel(float* __restrict__ out)
{
    extern __shared__ char smem[];
    const uint32_t sbase = smem_to_u32(smem);
    const int tid  = threadIdx.x;
    const int lane = tid & 31;
    const int wid  = tid >> 5;     // 0..15
    const int h    = wid & 1;      // K-half
    const int wq   = wid >> 1;     // 0..7 warp-tile id
    const int wm   = wq >> 2;      // 0..1
    const int wn   = wq & 3;       // 0..3
    const int m0 = blockIdx.y * BM;
    const int n0 = blockIdx.x * BN;

    float acc[4][4][4];
#pragma unroll
    for (int f = 0; f < 4; f++)
#pragma unroll
        for (int n = 0; n < 4; n++)
#pragma unroll
            for (int q = 0; q < 4; q++) acc[f][n][q] = 0.0f;

    // cp.async coords: thread t -> row t>>2 (0..127), 2 chunks of 16 B
    const int lrow = tid >> 2;
    const int j0   = (tid & 3) * 2;          // chunk indices j0, j0+1 (of 8)
    const uint32_t soA = (uint32_t)(lrow * 144 + j0 * 16);
    const size_t gx = (size_t)(m0 + lrow) * IN_F + j0 * 8;
    const size_t gw = (size_t)(n0 + lrow) * IN_F + j0 * 8;

    // ldmatrix fragment bases (fp16 units), offset by K-half h
    const uint32_t a_base = (uint32_t)((wm * 64 + (lane & 15)) * KPAD + (lane >> 4) * 8 + h * 32);
    const uint32_t b_base = (uint32_t)((wn * 32 + (lane & 7) + ((lane >> 4) & 1) * 8) * KPAD
                                       + ((lane >> 3) & 1) * 8 + h * 32);

#define LOAD_STAGE(ST, KT) do {                                    \
    uint32_t sb_ = sbase + (uint32_t)(ST) * STAGE_BYTES;           \
    size_t ko_ = (size_t)(KT) * BK;                                \
    cp16(sb_ + OFF_A + soA,      g_x_h + gx + ko_);                \
    cp16(sb_ + OFF_A + soA + 16, g_x_h + gx + ko_ + 8);            \
    cp16(sb_ + OFF_B + soA,      g_w_h + gw + ko_);                \
    cp16(sb_ + OFF_B + soA + 16, g_w_h + gw + ko_ + 8);            \
} while (0)

    LOAD_STAGE(0, 0); CP_COMMIT();
    LOAD_STAGE(1, 1); CP_COMMIT();

    int st = 0;
#pragma unroll 3
    for (int kt = 0; kt < NT; kt++) {
        CP_WAIT1();            // own groups: stage kt complete
        __syncthreads();       // publish stage kt; stage (kt-1)%3 free

        if (kt + 2 < NT) LOAD_STAGE((st + 2 >= NSTAGE) ? st + 2 - NSTAGE : st + 2, kt + 2);
        CP_COMMIT();           // fixed group accounting

        const uint32_t sb = sbase + (uint32_t)st * STAGE_BYTES;
        st++; if (st == NSTAGE) st = 0;

#pragma unroll
        for (int ks = 0; ks < 2; ks++) {
            uint32_t b[2][4];
#pragma unroll
            for (int p = 0; p < 2; p++)
                ldsm_x4(b[p], sb + OFF_B + (b_base + (uint32_t)(p * 16 * KPAD + ks * 16)) * 2);
#pragma unroll
            for (int f = 0; f < 4; f++) {
                uint32_t a[4];
                ldsm_x4(a, sb + OFF_A + (a_base + (uint32_t)(f * 16 * KPAD + ks * 16)) * 2);
#pragma unroll
                for (int n = 0; n < 4; n++) {
                    const int p = n >> 1, q = (n & 1) * 2;
                    mma_f16(acc[f][n], a, b[p][q], b[p][q + 1]);
                }
            }
        }
    }

    // ---- K-half reduction via smem (reuse stage memory) ----
    __syncthreads();           // all mainloop smem reads done
    {
        const uint32_t roff = (uint32_t)(wq * 8192 + lane * 256);
        if (h == 1) {
#pragma unroll
            for (int f = 0; f < 4; f++)
#pragma unroll
                for (int n = 0; n < 4; n++)
                    *(float4*)(smem + roff + (f * 4 + n) * 16) =
                        make_float4(acc[f][n][0], acc[f][n][1], acc[f][n][2], acc[f][n][3]);
        }
        __syncthreads();
        if (h == 0) {
#pragma unroll
            for (int f = 0; f < 4; f++)
#pragma unroll
                for (int n = 0; n < 4; n++) {
                    float4 v = *(const float4*)(smem + roff + (f * 4 + n) * 16);
                    acc[f][n][0] += v.x; acc[f][n][1] += v.y;
                    acc[f][n][2] += v.z; acc[f][n][3] += v.w;
                }
        }
    }

    // ---- epilogue (h==0 warps): add bias, write out ----
    if (h == 0) {
#pragma unroll
        for (int n = 0; n < 4; n++) {
            const int c = n0 + wn * 32 + n * 8 + (lane & 3) * 2;
            const float2 bs = *(const float2*)(g_bias + c);
#pragma unroll
            for (int f = 0; f < 4; f++) {
                const int r = m0 + wm * 64 + f * 16 + (lane >> 2);
                float2 v0, v1;
                v0.x = acc[f][n][0] + bs.x; v0.y = acc[f][n][1] + bs.y;
                v1.x = acc[f][n][2] + bs.x; v1.y = acc[f][n][3] + bs.y;
                *(float2*)(out + (size_t)r * OUT_F + c) = v0;
                *(float2*)(out + (size_t)(r + 8) * OUT_F + c) = v1;
            }
        }
    }
}

// ============================================================================
// launch
// ============================================================================
extern "C" void kernel_launch(void* const* d_in, const int* in_sizes, int n_in,
                              void* d_out, int out_size)
{
    const float* x    = (const float*)d_in[0];
    const float* wmu  = (const float*)d_in[1];
    const float* wrho = (const float*)d_in[2];
    const float* bmu  = (const float*)d_in[3];
    const float* brho = (const float*)d_in[4];
    const float* weps = (const float*)d_in[5];
    const float* beps = (const float*)d_in[6];
    float* out = (float*)d_out;

    prep_kernel<<<WBLK + XBLK + BBLK, 256>>>(x, wmu, wrho, bmu, brho, weps, beps);

    static bool attr_set = false;
    if (!attr_set) {
        cudaFuncSetAttribute(gemm_kernel, cudaFuncAttributeMaxDynamicSharedMemorySize, SMEM_SIZE);
        attr_set = true;
    }
    dim3 grid(OUT_F / BN, BATCH / BM);
    gemm_kernel<<<grid, 512, SMEM_SIZE>>>(out);
}

// round 11
// speedup vs baseline: 1.0914x; 1.0914x over previous
#include <cuda_runtime.h>
#include <cuda_fp16.h>
#include <cstdint>

// ============================================================================
// BayesianLinear on sm_103 (base ISA — tcgen05 blocked by compute_103 target).
// fp16 single-pass GEMM (rel_err ~3e-4 < 1e-3, validated R6):
//   w = mu + softplus(rho)*eps -> fp16;  x -> fp16
//   out = x_f16 @ w_f16^T  (fp32 accum)  + bias
// R10 -> R11: CTA tile 128x64, 256 thr, 8 warps of 32x32, regs ~70 ->
// 3 CTAs/SM (6 warps/SMSP for latency overlap) and 2048 CTAs (tail 12.5%->7%).
// Mainloop scheme identical to the proven R6 4-stage ring, 1 sync/kt.
// ============================================================================

#define IN_F   4096
#define OUT_F  4096
#define BATCH  4096

// ---------------- scratch (no cudaMalloc allowed) ----------------
__device__ __align__(16) __half g_w_h[(size_t)OUT_F * IN_F];
__device__ __align__(16) __half g_x_h[(size_t)BATCH * IN_F];
__device__ __align__(16) float  g_bias[OUT_F];

// ---------------- helpers ----------------
__device__ __forceinline__ uint32_t smem_to_u32(const void* p) {
    uint32_t a;
    asm("{ .reg .u64 t; cvta.to.shared.u64 t, %1; cvt.u32.u64 %0, t; }" : "=r"(a) : "l"(p));
    return a;
}

__device__ __forceinline__ void cp16(uint32_t saddr, const void* gptr) {
    size_t ga = __cvta_generic_to_global(gptr);
    asm volatile("cp.async.cg.shared.global [%0], [%1], 16;"
                 :: "r"(saddr), "l"(ga) : "memory");
}
#define CP_COMMIT() asm volatile("cp.async.commit_group;" ::: "memory")
#define CP_WAIT2()  asm volatile("cp.async.wait_group 2;" ::: "memory")

__device__ __forceinline__ void ldsm_x4(uint32_t (&r)[4], uint32_t saddr) {
    asm volatile("ldmatrix.sync.aligned.m8n8.x4.shared.b16 {%0,%1,%2,%3}, [%4];"
                 : "=r"(r[0]), "=r"(r[1]), "=r"(r[2]), "=r"(r[3]) : "r"(saddr));
}

__device__ __forceinline__ void mma_f16(float (&d)[4], const uint32_t (&a)[4],
                                        uint32_t b0, uint32_t b1) {
    asm volatile(
        "mma.sync.aligned.m16n8k16.row.col.f32.f16.f16.f32 "
        "{%0,%1,%2,%3}, {%4,%5,%6,%7}, {%8,%9}, {%0,%1,%2,%3};"
        : "+f"(d[0]), "+f"(d[1]), "+f"(d[2]), "+f"(d[3])
        : "r"(a[0]), "r"(a[1]), "r"(a[2]), "r"(a[3]), "r"(b0), "r"(b1));
}

__device__ __forceinline__ uint32_t pack_h2(float a, float b) {
    __half ha = __float2half_rn(a);
    __half hb = __float2half_rn(b);
    return (uint32_t)__half_as_ushort(ha) | ((uint32_t)__half_as_ushort(hb) << 16);
}

// ============================================================================
// Pass 1 (fused): weight -> fp16, x -> fp16, bias -> fp32
// ============================================================================
#define WBLK (OUT_F * (IN_F / 4) / 256)   // 16384
#define XBLK (BATCH * (IN_F / 4) / 256)   // 16384
#define BBLK (OUT_F / 256)                // 16

__global__ void __launch_bounds__(256) prep_kernel(
    const float* __restrict__ x,
    const float* __restrict__ wmu, const float* __restrict__ wrho,
    const float* __restrict__ bmu, const float* __restrict__ brho,
    const float* __restrict__ weps, const float* __restrict__ beps)
{
    int b = blockIdx.x;
    if (b < WBLK) {
        size_t i4 = (size_t)b * 256 + threadIdx.x;
        const float4 m = ((const float4*)wmu)[i4];
        const float4 r = ((const float4*)wrho)[i4];
        const float4 e = ((const float4*)weps)[i4];
        float w0 = m.x + (log1pf(expf(r.x)) + 1e-8f) * e.x;
        float w1 = m.y + (log1pf(expf(r.y)) + 1e-8f) * e.y;
        float w2 = m.z + (log1pf(expf(r.z)) + 1e-8f) * e.z;
        float w3 = m.w + (log1pf(expf(r.w)) + 1e-8f) * e.w;
        ((uint2*)g_w_h)[i4] = make_uint2(pack_h2(w0, w1), pack_h2(w2, w3));
    } else if (b < WBLK + XBLK) {
        size_t i4 = (size_t)(b - WBLK) * 256 + threadIdx.x;
        const float4 v = ((const float4*)x)[i4];
        ((uint2*)g_x_h)[i4] = make_uint2(pack_h2(v.x, v.y), pack_h2(v.z, v.w));
    } else {
        int i = (b - WBLK - XBLK) * 256 + threadIdx.x;
        g_bias[i] = bmu[i] + (log1pf(expf(brho[i])) + 1e-8f) * beps[i];
    }
}

// ============================================================================
// Pass 2: GEMM. CTA 128x64, BK=32 fp16, 4-stage ring, 1 sync/kt,
// 8 warps (4M x 2N, warp 32x32), 3 CTAs/SM.
// ============================================================================
#define BM 128
#define BN 64
#define BK 32
#define KPAD 40                   // fp16/row -> 80 B rows, conflict-free ldmatrix
#define ARR_A (128 * 80)          // 10240 B
#define ARR_B2 (64 * 80)          // 5120 B
#define OFF_A 0
#define OFF_B ARR_A
#define STAGE_BYTES (ARR_A + ARR_B2)   // 15360
#define NSTAGE 4
#define SMEM_SIZE (NSTAGE * STAGE_BYTES)   // 61440
#define NT (IN_F / BK)            // 128

__global__ void __launch_bounds__(256, 3) gemm_kernel(float* __restrict__ out)
{
    extern __shared__ char smem[];
    const uint32_t sbase = smem_to_u32(smem);
    const int tid  = threadIdx.x;
    const int lane = tid & 31;
    const int w    = tid >> 5;
    const int wm   = w >> 1;   // 0..3
    const int wn   = w & 1;    // 0..1
    const int m0 = blockIdx.y * BM;
    const int n0 = blockIdx.x * BN;

    float acc[2][4][4];
#pragma unroll
    for (int f = 0; f < 2; f++)
#pragma unroll
        for (int n = 0; n < 4; n++)
#pragma unroll
            for (int q = 0; q < 4; q++) acc[f][n][q] = 0.0f;

    // cp.async: 768 16B-chunks per stage (A: 512, B: 256) over 256 thr = 3 each.
    // chunk c = tid + k*256: rows are branch-free by construction:
    //   c0: A row tid>>2;  c1: A row tid>>2 + 64;  c2: B row tid>>2.
    const int row0 = tid >> 2;
    const int j16  = (tid & 3) << 4;          // byte offset of chunk in row
    const uint32_t s0 = (uint32_t)(OFF_A + row0 * 80 + j16);
    const uint32_t s1 = s0 + 64 * 80;
    const uint32_t s2 = (uint32_t)(OFF_B + row0 * 80 + j16);
    const __half* g0 = g_x_h + (size_t)(m0 + row0) * IN_F + (j16 >> 1);
    const __half* g1 = g0 + (size_t)64 * IN_F;
    const __half* g2 = g_w_h + (size_t)(n0 + row0) * IN_F + (j16 >> 1);

    // ldmatrix fragment bases (fp16 units)
    const uint32_t a_base = (uint32_t)((wm * 32 + (lane & 15)) * KPAD + (lane >> 4) * 8);
    const uint32_t b_base = (uint32_t)((wn * 32 + (lane & 7) + ((lane >> 4) & 1) * 8) * KPAD
                                       + ((lane >> 3) & 1) * 8);

#define LOAD_STAGE(ST, KT) do {                                    \
    uint32_t sb_ = sbase + (uint32_t)(ST) * STAGE_BYTES;           \
    size_t ko_ = (size_t)(KT) * BK;                                \
    cp16(sb_ + s0, g0 + ko_);                                      \
    cp16(sb_ + s1, g1 + ko_);                                      \
    cp16(sb_ + s2, g2 + ko_);                                      \
} while (0)

    LOAD_STAGE(0, 0); CP_COMMIT();
    LOAD_STAGE(1, 1); CP_COMMIT();
    LOAD_STAGE(2, 2); CP_COMMIT();

#pragma unroll 4
    for (int kt = 0; kt < NT; kt++) {
        CP_WAIT2();            // stage kt%4 complete (this thread)
        __syncthreads();       // publish; stage (kt-1)%4 readers done

        if (kt + 3 < NT) LOAD_STAGE((kt + 3) & 3, kt + 3);
        CP_COMMIT();           // fixed group accounting

        const uint32_t sb = sbase + (uint32_t)(kt & 3) * STAGE_BYTES;

#pragma unroll
        for (int ks = 0; ks < 2; ks++) {
            uint32_t b[2][4];
#pragma unroll
            for (int p = 0; p < 2; p++)
                ldsm_x4(b[p], sb + OFF_B + (b_base + (uint32_t)(p * 16 * KPAD + ks * 16)) * 2);
#pragma unroll
            for (int f = 0; f < 2; f++) {
                uint32_t a[4];
                ldsm_x4(a, sb + OFF_A + (a_base + (uint32_t)(f * 16 * KPAD + ks * 16)) * 2);
#pragma unroll
                for (int n = 0; n < 4; n++) {
                    const int p = n >> 1, q = (n & 1) * 2;
                    mma_f16(acc[f][n], a, b[p][q], b[p][q + 1]);
                }
            }
        }
    }

    // ---- epilogue: add bias, write out ----
#pragma unroll
    for (int n = 0; n < 4; n++) {
        const int c = n0 + wn * 32 + n * 8 + (lane & 3) * 2;
        const float2 bs = *(const float2*)(g_bias + c);
#pragma unroll
        for (int f = 0; f < 2; f++) {
            const int r = m0 + wm * 32 + f * 16 + (lane >> 2);
            float2 v0, v1;
            v0.x = acc[f][n][0] + bs.x; v0.y = acc[f][n][1] + bs.y;
            v1.x = acc[f][n][2] + bs.x; v1.y = acc[f][n][3] + bs.y;
            *(float2*)(out + (size_t)r * OUT_F + c) = v0;
            *(float2*)(out + (size_t)(r + 8) * OUT_F + c) = v1;
        }
    }
}

// ============================================================================
// launch
// ============================================================================
extern "C" void kernel_launch(void* const* d_in, const int* in_sizes, int n_in,
                              void* d_out, int out_size)
{
    const float* x    = (const float*)d_in[0];
    const float* wmu  = (const float*)d_in[1];
    const float* wrho = (const float*)d_in[2];
    const float* bmu  = (const float*)d_in[3];
    const float* brho = (const float*)d_in[4];
    const float* weps = (const float*)d_in[5];
    const float* beps = (const float*)d_in[6];
    float* out = (float*)d_out;

    prep_kernel<<<WBLK + XBLK + BBLK, 256>>>(x, wmu, wrho, bmu, brho, weps, beps);

    static bool attr_set = false;
    if (!attr_set) {
        cudaFuncSetAttribute(gemm_kernel, cudaFuncAttributeMaxDynamicSharedMemorySize, SMEM_SIZE);
        attr_set = true;
    }
    dim3 grid(OUT_F / BN, BATCH / BM);   // 64 x 32 = 2048 CTAs
    gemm_kernel<<<grid, 256, SMEM_SIZE>>>(out);
}